// round 8
// baseline (speedup 1.0000x reference)
#include <cuda_runtime.h>
#include <cuda_bf16.h>
#include <cstddef>

constexpr int B_   = 8;
constexpr int T_   = 32;
constexpr int NN   = 10;
constexpr int DOBJ = 2048;
constexpr int NV   = 157;
constexpr int NC   = 353;
constexpr int DE   = 512;
constexpr int DV   = 2048;
constexpr int ROWS_PB = T_ * NN;         // 320 rows per batch
constexpr int ROWS = B_ * ROWS_PB;       // 2560
constexpr int OUTW = DE + DV;            // 2560
constexpr int NCAP = 320;                // max distinct classes per batch
constexpr int SLOTS = 12;                // slots per hgemm pass
constexpr int RG   = 16;                 // scatter row-groups per batch
constexpr int RPG  = ROWS_PB / RG;       // 20 rows per group (10 per half)
constexpr int KQ   = 16;                 // hgemm k-chunks (128 k each)

// Scratch (static device globals; zero-initialized at load)
__device__ float g_Fc[(size_t)B_ * NCAP * DOBJ];   // compact class-sum features
__device__ float g_H [(size_t)B_ * NCAP * DE];     // Fc @ W (active slots)
__device__ int   g_cls[ROWS];
__device__ int   g_count[B_ * NC];                 // transient; re-zeroed by k_plan
__device__ int   g_cnt[B_ * NCAP];                 // compact per-slot counts
__device__ int   g_classlist[B_ * NC];
__device__ int   g_sorted[B_ * ROWS_PB];           // (slot<<16)|row, sorted by slot
__device__ int   g_u[B_];
__device__ float g_ctx[B_ * DV];

// ---------------------------------------------------------------------------
// K0: fused — blocks [0,64): temporal mean of fm_context
//             blocks [64,384): per-row class decode (warp per row)
__global__ void k_precls(const float* __restrict__ fm,
                         const int* __restrict__ obj_id) {  // grid 384, block 256
    if (blockIdx.x < 64) {
        int i = blockIdx.x * 256 + threadIdx.x;      // B_*DV = 16384
        int b = i / DV, d = i % DV;
        float s = 0.f;
        #pragma unroll
        for (int t = 0; t < T_; t++)
            s += fm[((size_t)(b * T_ + t)) * DV + d];
        g_ctx[b * DV + d] = s * (1.f / T_);
    } else {
        int blk = blockIdx.x - 64;                    // 320 blocks, 8 warps each
        int warp = blk * 8 + (threadIdx.x >> 5);      // row id 0..2559
        int lane = threadIdx.x & 31;
        const int* row = obj_id + (size_t)warp * NC;
        int best = -1;
        #pragma unroll
        for (int i = lane; i < NC; i += 32)
            if (row[i] != 0) best = i;
        #pragma unroll
        for (int o = 16; o > 0; o >>= 1)
            best = max(best, __shfl_xor_sync(0xffffffffu, best, o));
        int cls = (best < 0) ? 0 : best;
        if (lane == 0) {
            g_cls[warp] = cls;
            int b = warp / ROWS_PB;
            atomicAdd(&g_count[b * NC + cls], 1);
        }
    }
}

// ---------------------------------------------------------------------------
// K1: per-batch plan: compact class list, counting-sort rows by slot,
// compact counts, restore g_count to zero, zero active Fc/H rows.
__global__ void k_plan() {   // grid B_, block 384
    int b = blockIdx.x, tid = threadIdx.x;
    int w = tid >> 5, lane = tid & 31;
    __shared__ int wc[12], base[12], u_s;
    __shared__ int slotOf[NC];
    __shared__ int offs[NCAP];

    int cnt = (tid < NC) ? g_count[b * NC + tid] : 0;
    unsigned mask = __ballot_sync(0xffffffffu, cnt > 0);
    if (lane == 0) wc[w] = __popc(mask);
    __syncthreads();
    if (tid == 0) {
        int run = 0;
        for (int i = 0; i < 12; i++) { base[i] = run; run += wc[i]; }
        u_s = run; g_u[b] = run;
    }
    __syncthreads();
    if (cnt > 0) {
        int slot = base[w] + __popc(mask & ((1u << lane) - 1u));
        g_classlist[b * NC + slot] = tid;
        g_cnt[b * NCAP + slot] = cnt;
        slotOf[tid] = slot;
        g_count[b * NC + tid] = 0;        // restore zero state for next replay
    } else if (tid < NC) slotOf[tid] = -1;
    __syncthreads();
    int u = u_s;
    if (tid == 0) {  // slot start offsets
        int run = 0;
        for (int s = 0; s < u; s++) { offs[s] = run; run += g_cnt[b * NCAP + s]; }
    }
    __syncthreads();
    if (tid < ROWS_PB) {  // counting sort of rows by slot
        int cls = g_cls[b * ROWS_PB + tid];
        int s = slotOf[cls];
        int pos = atomicAdd(&offs[s], 1);
        g_sorted[b * ROWS_PB + pos] = (s << 16) | tid;
    }
    // zero active scratch: u rows of Fc (2048) and H (512)
    float4* pF = (float4*)(g_Fc + (size_t)b * NCAP * DOBJ);
    for (int i = tid; i < u * (DOBJ / 4); i += 384) pF[i] = make_float4(0,0,0,0);
    float4* pH = (float4*)(g_H + (size_t)b * NCAP * DE);
    for (int i = tid; i < u * (DE / 4); i += 384) pH[i] = make_float4(0,0,0,0);
}

// ---------------------------------------------------------------------------
// K2: slot-sorted scatter, 16 row-groups per batch for parallelism.
__global__ void k_scatter(const float* __restrict__ feat) {
    // grid (DOBJ/512=4, RG=16, B_), block 256
    int b = blockIdx.z, rg = blockIdx.y;
    int ch = blockIdx.x * 512;
    int tid = threadIdx.x;
    int half = tid >> 7;          // 2 halves of RPG/2 = 10 rows
    int l = tid & 127;            // 128 threads x float4 = 512 floats

    __shared__ int s_sorted[RPG];
    if (tid < RPG) s_sorted[tid] = g_sorted[b * ROWS_PB + rg * RPG + tid];
    __syncthreads();

    const float* fbase = feat + (size_t)b * ROWS_PB * DOBJ + ch + l * 4;
    int r = half * (RPG / 2), end = r + (RPG / 2);
    float4 acc = make_float4(0, 0, 0, 0);
    int cur = s_sorted[r] >> 16;
    #pragma unroll
    for (; r < end; r++) {
        int pk = s_sorted[r];
        int slot = pk >> 16, row = pk & 0xFFFF;
        if (slot != cur) {
            float* dst = g_Fc + ((size_t)b * NCAP + cur) * DOBJ + ch + l * 4;
            atomicAdd(dst + 0, acc.x); atomicAdd(dst + 1, acc.y);
            atomicAdd(dst + 2, acc.z); atomicAdd(dst + 3, acc.w);
            acc = make_float4(0, 0, 0, 0);
            cur = slot;
        }
        float4 v = *(const float4*)(fbase + (size_t)row * DOBJ);
        acc.x += v.x; acc.y += v.y; acc.z += v.z; acc.w += v.w;
    }
    float* dst = g_Fc + ((size_t)b * NCAP + cur) * DOBJ + ch + l * 4;
    atomicAdd(dst + 0, acc.x); atomicAdd(dst + 1, acc.y);
    atomicAdd(dst + 2, acc.z); atomicAdd(dst + 3, acc.w);
}

// ---------------------------------------------------------------------------
// K3: H[b,slot,:] += Fc[b,slot,kq*128:+128] @ W[kq*128:+128,:]
// grid (DE/32=16 colg, KQ=16, B_), block 256 (col 32 x kg 8).
// Thread tile: 12 slots x 1 col -> ~30 regs -> 6-8 blocks/SM (75-100% occ).
// Fs reads broadcast across the 32 col-lanes of a warp (one 16B LDS each).
__global__ void __launch_bounds__(256, 6) k_hgemm(const float* __restrict__ W) {
    __shared__ float Fs[SLOTS][128];          // 6 KB
    __shared__ float red[8][SLOTS][32];       // 12 KB
    int b = blockIdx.z;
    int kq = blockIdx.y;
    int colg = blockIdx.x * 32;
    int tid = threadIdx.x;
    int col = tid & 31;           // column within 32-col tile
    int kg = tid >> 5;            // 0..7
    int u = g_u[b];

    for (int g0 = 0; g0 < u; g0 += SLOTS) {
        int ns = min(SLOTS, u - g0);
        for (int j = tid; j < SLOTS * 32; j += 256) {   // float4 units
            int s = j >> 5, kk = j & 31;
            float4 v = (s < ns)
                ? ((const float4*)(g_Fc + ((size_t)b * NCAP + g0 + s) * DOBJ + kq * 128))[kk]
                : make_float4(0, 0, 0, 0);
            ((float4*)Fs[s])[kk] = v;
        }
        __syncthreads();

        float acc[SLOTS];
        #pragma unroll
        for (int s = 0; s < SLOTS; s++) acc[s] = 0.f;

        // k handled by this thread: kbase = kg*4 + i*32, i in [0,4)
        const float* Wbase = W + ((size_t)(kq * 128 + kg * 4)) * DE + colg + col;
        float w0 = Wbase[0 * DE];
        float w1 = Wbase[1 * DE];
        float w2 = Wbase[2 * DE];
        float w3 = Wbase[3 * DE];
        #pragma unroll
        for (int i = 0; i < 4; i++) {
            float n0, n1, n2, n3;
            if (i < 3) {                       // prefetch next iteration's W
                const float* Wn = Wbase + (size_t)(i + 1) * 32 * DE;
                n0 = Wn[0 * DE]; n1 = Wn[1 * DE];
                n2 = Wn[2 * DE]; n3 = Wn[3 * DE];
            }
            int kbase = kg * 4 + i * 32;
            #pragma unroll
            for (int s = 0; s < SLOTS; s++) {
                float4 f = *(const float4*)&Fs[s][kbase];
                acc[s] += f.x * w0 + f.y * w1 + f.z * w2 + f.w * w3;
            }
            w0 = n0; w1 = n1; w2 = n2; w3 = n3;
        }

        #pragma unroll
        for (int s = 0; s < SLOTS; s++) red[kg][s][col] = acc[s];
        __syncthreads();
        for (int j = tid; j < ns * 32; j += 256) {
            int s = j >> 5, c2 = j & 31;
            float h = 0.f;
            #pragma unroll
            for (int k2 = 0; k2 < 8; k2++) h += red[k2][s][c2];
            atomicAdd(&g_H[((size_t)b * NCAP + g0 + s) * DE + colg + c2], h);
        }
        __syncthreads();
    }
}

// ---------------------------------------------------------------------------
// K4: assemble output rows
__global__ void k_out(const float* __restrict__ Ao2v,
                      const float* __restrict__ bias,
                      float* __restrict__ out) {  // grid (NV, B_), 256
    int v = blockIdx.x, b = blockIdx.y;
    int tid = threadIdx.x;
    int u = g_u[b];
    float sbv = 0.f, a0 = 0.f, a1 = 0.f;
    for (int s = 0; s < u; s++) {
        int c = g_classlist[b * NC + s];
        float a = Ao2v[(size_t)v * NC + c];
        sbv += a * (float)g_cnt[b * NCAP + s];
        const float* Hr = g_H + ((size_t)b * NCAP + s) * DE;
        a0 += a * Hr[tid];
        a1 += a * Hr[tid + 256];
    }
    const float inv = 1.f / T_;
    float* orow = out + ((size_t)b * NV + v) * OUTW;
    orow[tid]       = (a0 + sbv * bias[tid]) * inv;
    orow[tid + 256] = (a1 + sbv * bias[tid + 256]) * inv;
    const float4* cm = (const float4*)(g_ctx + (size_t)b * DV);
    float4* od = (float4*)(orow + DE);
    #pragma unroll
    for (int j = tid; j < DV / 4; j += 256) od[j] = cm[j];
}

// ---------------------------------------------------------------------------
extern "C" void kernel_launch(void* const* d_in, const int* in_sizes, int n_in,
                              void* d_out, int out_size) {
    const float* feat  = (const float*)d_in[0];
    const float* fm    = (const float*)d_in[1];
    const int*   objid = (const int*)  d_in[2];
    const float* W     = (const float*)d_in[3];
    const float* bias  = (const float*)d_in[4];
    const float* Ao2v  = (const float*)d_in[5];
    float* out = (float*)d_out;

    k_precls <<<384, 256>>>(fm, objid);
    k_plan   <<<B_, 384>>>();
    k_scatter<<<dim3(DOBJ / 512, RG, B_), 256>>>(feat);
    k_hgemm  <<<dim3(DE / 32, KQ, B_), 256>>>(W);
    k_out    <<<dim3(NV, B_), 256>>>(Ao2v, bias, out);
}

// round 9
// speedup vs baseline: 1.1168x; 1.1168x over previous
#include <cuda_runtime.h>
#include <cuda_bf16.h>
#include <cstddef>

constexpr int B_   = 8;
constexpr int T_   = 32;
constexpr int NN   = 10;
constexpr int DOBJ = 2048;
constexpr int NV   = 157;
constexpr int NC   = 353;
constexpr int DE   = 512;
constexpr int DV   = 2048;
constexpr int ROWS_PB = T_ * NN;         // 320 rows per batch
constexpr int ROWS = B_ * ROWS_PB;       // 2560
constexpr int OUTW = DE + DV;            // 2560
constexpr int NCAP = 320;                // max distinct classes per batch
constexpr int SLOTS = 12;                // slots per hgemm pass
constexpr int RG   = 16;                 // scatter row-groups per batch
constexpr int RPG  = ROWS_PB / RG;       // 20 rows per group (10 per half)
constexpr int KQ   = 16;                 // hgemm k-chunks (128 k each)

// Packed f32x2 helpers (sm_103a FFMA2 path — PTX only, ptxas never auto-fuses)
#define FMA2(acc, a, b) \
    asm("fma.rn.f32x2 %0, %1, %2, %0;" : "+l"(acc) : "l"(a), "l"(b))
#define ADD2(d, a, b) \
    asm("add.rn.f32x2 %0, %1, %2;" : "=l"(d) : "l"(a), "l"(b))
#define PACK_DUP(d, f) \
    asm("mov.b64 %0, {%1, %1};" : "=l"(d) : "r"(__float_as_uint(f)))
#define UNPACK2(lo, hi, v) \
    asm("mov.b64 {%0, %1}, %2;" : "=r"(lo), "=r"(hi) : "l"(v))

// Scratch (static device globals; zero-initialized at load)
__device__ float g_Fc[(size_t)B_ * NCAP * DOBJ];   // compact class-sum features
__device__ float g_H [(size_t)B_ * NCAP * DE];     // Fc @ W (active slots)
__device__ int   g_cls[ROWS];
__device__ int   g_count[B_ * NC];                 // transient; re-zeroed by k_plan
__device__ int   g_cnt[B_ * NCAP];                 // compact per-slot counts
__device__ int   g_classlist[B_ * NC];
__device__ int   g_sorted[B_ * ROWS_PB];           // (slot<<16)|row, sorted by slot
__device__ int   g_u[B_];
__device__ float g_ctx[B_ * DV];

// ---------------------------------------------------------------------------
// K0: fused — blocks [0,64): temporal mean of fm_context
//             blocks [64,384): per-row class decode (warp per row)
__global__ void k_precls(const float* __restrict__ fm,
                         const int* __restrict__ obj_id) {  // grid 384, block 256
    if (blockIdx.x < 64) {
        int i = blockIdx.x * 256 + threadIdx.x;      // B_*DV = 16384
        int b = i / DV, d = i % DV;
        float s = 0.f;
        #pragma unroll
        for (int t = 0; t < T_; t++)
            s += fm[((size_t)(b * T_ + t)) * DV + d];
        g_ctx[b * DV + d] = s * (1.f / T_);
    } else {
        int blk = blockIdx.x - 64;                    // 320 blocks, 8 warps each
        int warp = blk * 8 + (threadIdx.x >> 5);      // row id 0..2559
        int lane = threadIdx.x & 31;
        const int* row = obj_id + (size_t)warp * NC;
        int best = -1;
        #pragma unroll
        for (int i = lane; i < NC; i += 32)
            if (row[i] != 0) best = i;
        #pragma unroll
        for (int o = 16; o > 0; o >>= 1)
            best = max(best, __shfl_xor_sync(0xffffffffu, best, o));
        int cls = (best < 0) ? 0 : best;
        if (lane == 0) {
            g_cls[warp] = cls;
            int b = warp / ROWS_PB;
            atomicAdd(&g_count[b * NC + cls], 1);
        }
    }
}

// ---------------------------------------------------------------------------
// K1: per-batch plan: compact class list, counting-sort rows by slot,
// compact counts, restore g_count to zero, zero active Fc/H rows.
__global__ void k_plan() {   // grid B_, block 384
    int b = blockIdx.x, tid = threadIdx.x;
    int w = tid >> 5, lane = tid & 31;
    __shared__ int wc[12], base[12], u_s;
    __shared__ int slotOf[NC];
    __shared__ int offs[NCAP];

    int cnt = (tid < NC) ? g_count[b * NC + tid] : 0;
    unsigned mask = __ballot_sync(0xffffffffu, cnt > 0);
    if (lane == 0) wc[w] = __popc(mask);
    __syncthreads();
    if (tid == 0) {
        int run = 0;
        for (int i = 0; i < 12; i++) { base[i] = run; run += wc[i]; }
        u_s = run; g_u[b] = run;
    }
    __syncthreads();
    if (cnt > 0) {
        int slot = base[w] + __popc(mask & ((1u << lane) - 1u));
        g_classlist[b * NC + slot] = tid;
        g_cnt[b * NCAP + slot] = cnt;
        slotOf[tid] = slot;
        g_count[b * NC + tid] = 0;        // restore zero state for next replay
    } else if (tid < NC) slotOf[tid] = -1;
    __syncthreads();
    int u = u_s;
    if (tid == 0) {  // slot start offsets
        int run = 0;
        for (int s = 0; s < u; s++) { offs[s] = run; run += g_cnt[b * NCAP + s]; }
    }
    __syncthreads();
    if (tid < ROWS_PB) {  // counting sort of rows by slot
        int cls = g_cls[b * ROWS_PB + tid];
        int s = slotOf[cls];
        int pos = atomicAdd(&offs[s], 1);
        g_sorted[b * ROWS_PB + pos] = (s << 16) | tid;
    }
    // zero active scratch: u rows of Fc (2048) and H (512)
    float4* pF = (float4*)(g_Fc + (size_t)b * NCAP * DOBJ);
    for (int i = tid; i < u * (DOBJ / 4); i += 384) pF[i] = make_float4(0,0,0,0);
    float4* pH = (float4*)(g_H + (size_t)b * NCAP * DE);
    for (int i = tid; i < u * (DE / 4); i += 384) pH[i] = make_float4(0,0,0,0);
}

// ---------------------------------------------------------------------------
// K2: slot-sorted scatter, 16 row-groups per batch for parallelism.
__global__ void k_scatter(const float* __restrict__ feat) {
    // grid (DOBJ/512=4, RG=16, B_), block 256
    int b = blockIdx.z, rg = blockIdx.y;
    int ch = blockIdx.x * 512;
    int tid = threadIdx.x;
    int half = tid >> 7;          // 2 halves of RPG/2 = 10 rows
    int l = tid & 127;            // 128 threads x float4 = 512 floats

    __shared__ int s_sorted[RPG];
    if (tid < RPG) s_sorted[tid] = g_sorted[b * ROWS_PB + rg * RPG + tid];
    __syncthreads();

    const float* fbase = feat + (size_t)b * ROWS_PB * DOBJ + ch + l * 4;
    int r = half * (RPG / 2), end = r + (RPG / 2);
    float4 acc = make_float4(0, 0, 0, 0);
    int cur = s_sorted[r] >> 16;
    #pragma unroll
    for (; r < end; r++) {
        int pk = s_sorted[r];
        int slot = pk >> 16, row = pk & 0xFFFF;
        if (slot != cur) {
            float* dst = g_Fc + ((size_t)b * NCAP + cur) * DOBJ + ch + l * 4;
            atomicAdd(dst + 0, acc.x); atomicAdd(dst + 1, acc.y);
            atomicAdd(dst + 2, acc.z); atomicAdd(dst + 3, acc.w);
            acc = make_float4(0, 0, 0, 0);
            cur = slot;
        }
        float4 v = *(const float4*)(fbase + (size_t)row * DOBJ);
        acc.x += v.x; acc.y += v.y; acc.z += v.z; acc.w += v.w;
    }
    float* dst = g_Fc + ((size_t)b * NCAP + cur) * DOBJ + ch + l * 4;
    atomicAdd(dst + 0, acc.x); atomicAdd(dst + 1, acc.y);
    atomicAdd(dst + 2, acc.z); atomicAdd(dst + 3, acc.w);
}

// ---------------------------------------------------------------------------
// K3: H[b,slot,:] += Fc[b,slot,kq*128:+128] @ W[kq*128:+128,:]
// grid (DE/64=8 colg, KQ=16, B_), block 128 (32 col-lanes x 4 kg).
// Packed-math version: Fs stored TRANSPOSED [k][16] so an ulonglong2 LDS.128
// yields slot-pairs pre-packed for fma.rn.f32x2 (FFMA2). Accumulators hold
// (slot 2p, slot 2p+1) pairs per column; per k: 3 LDS.128 + 1 LDG.64 +
// 2 packs + 12 FFMA2 = 24 MACs. Reduction stays packed until final atomics.
__global__ void __launch_bounds__(128, 8) k_hgemm(const float* __restrict__ W) {
    __shared__ float Fs[128][16];                         // transposed, padded: 8 KB
    __shared__ unsigned long long red[4][6][64];          // packed partials: 12 KB
    int b = blockIdx.z;
    int kq = blockIdx.y;
    int colg = blockIdx.x * 64;
    int tid = threadIdx.x;
    int col = tid & 31;           // lane -> cols colg + 2*col, +1
    int kg = tid >> 5;            // 0..3
    int u = g_u[b];

    for (int g0 = 0; g0 < u; g0 += SLOTS) {
        int ns = min(SLOTS, u - g0);
        // transposed cooperative load: j -> (slot s, 4k-group kk4)
        for (int j = tid; j < SLOTS * 32; j += 128) {
            int s = j % 12, kk4 = j / 12;
            float4 v = (s < ns)
                ? ((const float4*)(g_Fc + ((size_t)b * NCAP + g0 + s) * DOBJ + kq * 128))[kk4]
                : make_float4(0, 0, 0, 0);
            Fs[kk4 * 4 + 0][s] = v.x;
            Fs[kk4 * 4 + 1][s] = v.y;
            Fs[kk4 * 4 + 2][s] = v.z;
            Fs[kk4 * 4 + 3][s] = v.w;
        }
        __syncthreads();

        unsigned long long acc2[6][2];
        #pragma unroll
        for (int p = 0; p < 6; p++) { acc2[p][0] = 0ull; acc2[p][1] = 0ull; }

        // this thread's k: kg*4 + i*16 + j, i<8, j<4
        const float* Wb = W + (size_t)(kq * 128 + kg * 4) * DE + colg + col * 2;
        #pragma unroll 2
        for (int i = 0; i < 8; i++) {
            #pragma unroll
            for (int j = 0; j < 4; j++) {
                int krow = kg * 4 + i * 16 + j;
                float2 w = *(const float2*)&Wb[(size_t)(i * 16 + j) * DE];
                unsigned long long wp0, wp1;
                PACK_DUP(wp0, w.x);
                PACK_DUP(wp1, w.y);
                const ulonglong2* fp = (const ulonglong2*)&Fs[krow][0];
                ulonglong2 q0 = fp[0];   // slots 0-3 (2 packed pairs)
                ulonglong2 q1 = fp[1];   // slots 4-7
                ulonglong2 q2 = fp[2];   // slots 8-11
                FMA2(acc2[0][0], q0.x, wp0); FMA2(acc2[0][1], q0.x, wp1);
                FMA2(acc2[1][0], q0.y, wp0); FMA2(acc2[1][1], q0.y, wp1);
                FMA2(acc2[2][0], q1.x, wp0); FMA2(acc2[2][1], q1.x, wp1);
                FMA2(acc2[3][0], q1.y, wp0); FMA2(acc2[3][1], q1.y, wp1);
                FMA2(acc2[4][0], q2.x, wp0); FMA2(acc2[4][1], q2.x, wp1);
                FMA2(acc2[5][0], q2.y, wp0); FMA2(acc2[5][1], q2.y, wp1);
            }
        }

        #pragma unroll
        for (int p = 0; p < 6; p++) {
            red[kg][p][col * 2]     = acc2[p][0];
            red[kg][p][col * 2 + 1] = acc2[p][1];
        }
        __syncthreads();
        for (int j = tid; j < 6 * 64; j += 128) {   // 3 iters
            int p = j >> 6, cidx = j & 63;
            unsigned long long s01, s23, h2;
            ADD2(s01, red[0][p][cidx], red[1][p][cidx]);
            ADD2(s23, red[2][p][cidx], red[3][p][cidx]);
            ADD2(h2, s01, s23);
            unsigned int lo, hi;
            UNPACK2(lo, hi, h2);
            int s0 = 2 * p, s1 = 2 * p + 1;
            if (s0 < ns)
                atomicAdd(&g_H[((size_t)b * NCAP + g0 + s0) * DE + colg + cidx],
                          __uint_as_float(lo));
            if (s1 < ns)
                atomicAdd(&g_H[((size_t)b * NCAP + g0 + s1) * DE + colg + cidx],
                          __uint_as_float(hi));
        }
        __syncthreads();
    }
}

// ---------------------------------------------------------------------------
// K4: assemble output rows
__global__ void k_out(const float* __restrict__ Ao2v,
                      const float* __restrict__ bias,
                      float* __restrict__ out) {  // grid (NV, B_), 256
    int v = blockIdx.x, b = blockIdx.y;
    int tid = threadIdx.x;
    int u = g_u[b];
    float sbv = 0.f, a0 = 0.f, a1 = 0.f;
    for (int s = 0; s < u; s++) {
        int c = g_classlist[b * NC + s];
        float a = Ao2v[(size_t)v * NC + c];
        sbv += a * (float)g_cnt[b * NCAP + s];
        const float* Hr = g_H + ((size_t)b * NCAP + s) * DE;
        a0 += a * Hr[tid];
        a1 += a * Hr[tid + 256];
    }
    const float inv = 1.f / T_;
    float* orow = out + ((size_t)b * NV + v) * OUTW;
    orow[tid]       = (a0 + sbv * bias[tid]) * inv;
    orow[tid + 256] = (a1 + sbv * bias[tid + 256]) * inv;
    const float4* cm = (const float4*)(g_ctx + (size_t)b * DV);
    float4* od = (float4*)(orow + DE);
    #pragma unroll
    for (int j = tid; j < DV / 4; j += 256) od[j] = cm[j];
}

// ---------------------------------------------------------------------------
extern "C" void kernel_launch(void* const* d_in, const int* in_sizes, int n_in,
                              void* d_out, int out_size) {
    const float* feat  = (const float*)d_in[0];
    const float* fm    = (const float*)d_in[1];
    const int*   objid = (const int*)  d_in[2];
    const float* W     = (const float*)d_in[3];
    const float* bias  = (const float*)d_in[4];
    const float* Ao2v  = (const float*)d_in[5];
    float* out = (float*)d_out;

    k_precls <<<384, 256>>>(fm, objid);
    k_plan   <<<B_, 384>>>();
    k_scatter<<<dim3(DOBJ / 512, RG, B_), 256>>>(feat);
    k_hgemm  <<<dim3(DE / 64, KQ, B_), 128>>>(W);
    k_out    <<<dim3(NV, B_), 256>>>(Ao2v, bias, out);
}